// round 15
// baseline (speedup 1.0000x reference)
#include <cuda_runtime.h>
#include <cuda_fp16.h>
#include <math.h>
#include <stdint.h>

#define TOKENS 4096
#define NE 8
#define NPAIR 8192
#define KD 1024
#define NMAT 27            // 0 sg, 1 su, 2 sd, 3..10 eg, 11..18 eu, 19..26 ed

typedef __half half_t;

// ---------------- scratch (device globals; no allocations allowed) ----------
__device__ __align__(16) half_t g_xh[(size_t)TOKENS * KD];          // x fp16
__device__ __align__(16) half_t g_wT[(size_t)NMAT * KD * KD];       // W^T fp16
__device__ __align__(16) half_t g_hs[(size_t)TOKENS * KD];          // shared hidden
__device__ __align__(16) half_t g_hr[(size_t)NPAIR * KD];           // routed hidden
__device__ __align__(16) float g_o_shared[(size_t)TOKENS * KD];
__device__ __align__(16) float g_o_routed[(size_t)NPAIR * KD];
__device__ float g_topw[NPAIR];
__device__ int   g_counts[NE];
__device__ int   g_lists[NE * TOKENS];

// ---------------- PTX helpers (portable ISA, sm_80+) -------------------------
__device__ __forceinline__ uint32_t smem_to_u32(const void* p) {
    uint32_t a;
    asm("{ .reg .u64 t; cvta.to.shared.u64 t, %1; cvt.u32.u64 %0, t; }" : "=r"(a) : "l"(p));
    return a;
}
__device__ __forceinline__ void cp16(uint32_t dst, const void* src) {
    asm volatile("cp.async.cg.shared.global [%0], [%1], 16;" :: "r"(dst), "l"(src));
}
#define CP_COMMIT() asm volatile("cp.async.commit_group;" ::: "memory")
#define CP_WAIT1()  asm volatile("cp.async.wait_group 1;" ::: "memory")
#define CP_WAIT0()  asm volatile("cp.async.wait_group 0;" ::: "memory")

__device__ __forceinline__ void ldsm4(uint32_t* r, uint32_t addr) {
    asm volatile("ldmatrix.sync.aligned.m8n8.x4.shared.b16 {%0,%1,%2,%3}, [%4];"
                 : "=r"(r[0]), "=r"(r[1]), "=r"(r[2]), "=r"(r[3]) : "r"(addr));
}
__device__ __forceinline__ void mma16816(float* c, const uint32_t* a,
                                         uint32_t b0, uint32_t b1) {
    asm volatile("mma.sync.aligned.m16n8k16.row.col.f32.f16.f16.f32 "
                 "{%0,%1,%2,%3}, {%4,%5,%6,%7}, {%8,%9}, {%0,%1,%2,%3};"
                 : "+f"(c[0]), "+f"(c[1]), "+f"(c[2]), "+f"(c[3])
                 : "r"(a[0]), "r"(a[1]), "r"(a[2]), "r"(a[3]), "r"(b0), "r"(b1));
}
__device__ __forceinline__ uint32_t pack_h2(float a, float b) {
    __half2 h = __floats2half2_rn(a, b);
    return *(uint32_t*)&h;
}

// ---------------- setup -------------------------------------------------------
__global__ void zero_counts_k() { if (threadIdx.x < NE) g_counts[threadIdx.x] = 0; }

// fused: x fp32 -> fp16 conversion AND router softmax/top2/compaction
__global__ __launch_bounds__(256)
void convert_router_k(const float* __restrict__ x, const float* __restrict__ rw) {
    int t = (blockIdx.x * blockDim.x + threadIdx.x) >> 5;
    int lane = threadIdx.x & 31;
    const float* xr = x + (size_t)t * KD;
    float acc[NE];
#pragma unroll
    for (int e = 0; e < NE; e++) acc[e] = 0.f;
#pragma unroll
    for (int i = 0; i < 8; i++) {
        int h = lane * 4 + i * 128;
        float4 v = *(const float4*)(xr + h);
        uint2 p;
        p.x = pack_h2(v.x, v.y);
        p.y = pack_h2(v.z, v.w);
        *(uint2*)(g_xh + (size_t)t * KD + h) = p;
#pragma unroll
        for (int e = 0; e < NE; e++) {
            float4 w = *(const float4*)(rw + e * KD + h);
            acc[e] = fmaf(v.x, w.x, acc[e]);
            acc[e] = fmaf(v.y, w.y, acc[e]);
            acc[e] = fmaf(v.z, w.z, acc[e]);
            acc[e] = fmaf(v.w, w.w, acc[e]);
        }
    }
#pragma unroll
    for (int e = 0; e < NE; e++)
#pragma unroll
        for (int o = 16; o > 0; o >>= 1)
            acc[e] += __shfl_down_sync(0xffffffffu, acc[e], o);
    if (lane == 0) {
        float mx = acc[0];
#pragma unroll
        for (int e = 1; e < NE; e++) mx = fmaxf(mx, acc[e]);
        float s[NE]; float sum = 0.f;
#pragma unroll
        for (int e = 0; e < NE; e++) { s[e] = expf(acc[e] - mx); sum += s[e]; }
        float inv = 1.f / sum;
        int i1 = 0; float v1 = s[0];
#pragma unroll
        for (int e = 1; e < NE; e++) if (s[e] > v1) { v1 = s[e]; i1 = e; }
        int i2 = -1; float v2 = -1.f;
#pragma unroll
        for (int e = 0; e < NE; e++) if (e != i1 && s[e] > v2) { v2 = s[e]; i2 = e; }
        g_topw[t * 2 + 0] = v1 * inv;
        g_topw[t * 2 + 1] = v2 * inv;
        int s1 = atomicAdd(&g_counts[i1], 1); g_lists[i1 * TOKENS + s1] = t * 2;
        int s2 = atomicAdd(&g_counts[i2], 1); g_lists[i2 * TOKENS + s2] = t * 2 + 1;
    }
}

// transpose weights: [K][N] fp32 -> [n][k] fp16
__global__ __launch_bounds__(256) void transpose_w_k(
    const float* __restrict__ sg, const float* __restrict__ su,
    const float* __restrict__ sd, const float* __restrict__ eg,
    const float* __restrict__ eu, const float* __restrict__ ed)
{
    __shared__ float t[64][33];
    int slot = blockIdx.z;
    const float* src;
    if      (slot == 0) src = sg;
    else if (slot == 1) src = su;
    else if (slot == 2) src = sd;
    else if (slot < 11) src = eg + (size_t)(slot - 3) * KD * KD;
    else if (slot < 19) src = eu + (size_t)(slot - 11) * KD * KD;
    else                src = ed + (size_t)(slot - 19) * KD * KD;
    int k0 = blockIdx.x * 64, n0 = blockIdx.y * 32;
    int tx = threadIdx.x & 31, ty = threadIdx.x >> 5;
#pragma unroll
    for (int i = 0; i < 8; i++) {
        int r = ty + i * 8;
        t[r][tx] = src[(size_t)(k0 + r) * KD + n0 + tx];
    }
    __syncthreads();
    half_t* oh = g_wT + (size_t)slot * KD * KD;
#pragma unroll
    for (int i = 0; i < 4; i++) {
        int r = ty + i * 8;
        ((uint32_t*)(oh + (size_t)(n0 + r) * KD + k0))[tx] =
            pack_h2(t[2 * tx][r], t[2 * tx + 1][r]);
    }
}

// ============================================================================
// GEMM kernels — 128-row M tiles, 128-thread CTAs, 2m x 2n warps of 64x64,
// 2 CTAs/SM. y index: [0,32) shared (m0 = y*128); [32, 32+256) routed.
// ============================================================================
#define STAGE_B 32768

// ---------------- mlp1: dual gate+up GEMM with fused SwiGLU ------------------
// CTA tile 128m x 64n per matrix. stage: A 16K | Bg 8K | Bu 8K = 32 KB.
__device__ __forceinline__ void stage_load_d(
    uint32_t sbase, const half_t* __restrict__ A, const half_t* __restrict__ Wg,
    const half_t* __restrict__ Wu, const int* s_src, int m0, int n0, int k0, int tid)
{
#pragma unroll
    for (int i = 0; i < 8; i++) {
        int chunk = tid + i * 128;
        int row = chunk >> 3, cc = chunk & 7;   // row 0..127
        uint32_t off = row * 128 + ((cc * 16) ^ ((row & 7) << 4));
        int arow = s_src ? s_src[row] : (m0 + row);
        cp16(sbase + off, A + (size_t)arow * KD + k0 + cc * 8);
    }
#pragma unroll
    for (int i = 0; i < 4; i++) {
        int chunk = tid + i * 128;
        int row = chunk >> 3, cc = chunk & 7;   // row 0..63
        uint32_t off = row * 128 + ((cc * 16) ^ ((row & 7) << 4));
        cp16(sbase + 16384 + off, Wg + (size_t)(n0 + row) * KD + k0 + cc * 8);
        cp16(sbase + 24576 + off, Wu + (size_t)(n0 + row) * KD + k0 + cc * 8);
    }
}

__global__ __launch_bounds__(128, 2)
void mlp1_k(const half_t* __restrict__ A, half_t* __restrict__ Hs,
            half_t* __restrict__ Hr)
{
    extern __shared__ __align__(1024) char dynsm[];
    __shared__ int s_src[128];
    __shared__ int s_dst[128];

    const int tid = threadIdx.x;
    const int wid = tid >> 5, lane = tid & 31;
    const int n0 = blockIdx.x * 64;
    const int by = blockIdx.y;

    const half_t* Wg;
    const half_t* Wu;
    half_t* H;
    bool gather;
    int m0;
    if (by < 32) {
        gather = false;
        m0 = by * 128;
        Wg = g_wT;                         // slot 0
        Wu = g_wT + (size_t)1 * KD * KD;   // slot 1
        H = Hs;
    } else {
        gather = true;
        int e = (by - 32) >> 5;
        int mtile = (by - 32) & 31;
        int count = g_counts[e];
        if (mtile * 128 >= count) return;
        m0 = 0;
        Wg = g_wT + (size_t)(3 + e) * KD * KD;
        Wu = g_wT + (size_t)(11 + e) * KD * KD;
        H = Hr;
        {
            int idx = mtile * 128 + tid;
            if (idx < count) {
                int p = g_lists[e * TOKENS + idx];
                s_dst[tid] = p;
                s_src[tid] = p >> 1;
            } else { s_dst[tid] = -1; s_src[tid] = 0; }
        }
        __syncthreads();
    }
    const int* srcp = gather ? s_src : (const int*)nullptr;
    const uint32_t smbase = smem_to_u32(dynsm);

    const int warpM = wid >> 1, warpN = wid & 1;   // 2m x 2n; warp 64m x 32n/matrix
    const int mi = lane >> 3, ri = lane & 7;
    const int aRowBase = warpM * 64 + ((mi & 1) << 3) + ri;
    const int aKoff = (mi >> 1) << 4;
    const uint32_t aSwz = (aRowBase & 7) << 4;
    const int bRowBase = warpN * 32 + ((mi >> 1) << 3) + ri;
    const int bKoff = (mi & 1) << 4;
    const uint32_t bSwz = (bRowBase & 7) << 4;

    float accg[4][4][4], accu[4][4][4];
#pragma unroll
    for (int i = 0; i < 4; i++)
#pragma unroll
        for (int j = 0; j < 4; j++)
#pragma unroll
            for (int q = 0; q < 4; q++) { accg[i][j][q] = 0.f; accu[i][j][q] = 0.f; }

    stage_load_d(smbase, A, Wg, Wu, srcp, m0, n0, 0, tid);
    CP_COMMIT();

    for (int kt = 0; kt < 16; kt++) {
        const uint32_t buf = smbase + (kt & 1) * STAGE_B;
        if (kt < 15) {
            stage_load_d(smbase + ((kt + 1) & 1) * STAGE_B, A, Wg, Wu, srcp,
                         m0, n0, (kt + 1) * 64, tid);
            CP_COMMIT();
            CP_WAIT1();
        } else {
            CP_WAIT0();
        }
        __syncthreads();
#pragma unroll
        for (int ks = 0; ks < 4; ks++) {
            uint32_t a[4][4], bg[2][4], bu[2][4];
#pragma unroll
            for (int ms = 0; ms < 4; ms++) {
                uint32_t off = (uint32_t)(aRowBase + ms * 16) * 128
                             + (((uint32_t)(ks * 32 + aKoff)) ^ aSwz);
                ldsm4(a[ms], buf + off);
            }
#pragma unroll
            for (int np = 0; np < 2; np++) {
                uint32_t off = (uint32_t)(bRowBase + np * 16) * 128
                             + (((uint32_t)(ks * 32 + bKoff)) ^ bSwz);
                ldsm4(bg[np], buf + 16384 + off);
                ldsm4(bu[np], buf + 24576 + off);
            }
#pragma unroll
            for (int ms = 0; ms < 4; ms++)
#pragma unroll
                for (int ns = 0; ns < 4; ns++) {
                    int np = ns >> 1, h = (ns & 1) << 1;
                    mma16816(accg[ms][ns], a[ms], bg[np][h], bg[np][h + 1]);
                    mma16816(accu[ms][ns], a[ms], bu[np][h], bu[np][h + 1]);
                }
        }
        __syncthreads();
    }

    const int rbase = lane >> 2;
    const int cbase = (lane & 3) * 2;
#pragma unroll
    for (int ms = 0; ms < 4; ms++) {
        int lm = warpM * 64 + ms * 16 + rbase;
#pragma unroll
        for (int half = 0; half < 2; half++) {
            int lmr = lm + half * 8;
            int dst = gather ? s_dst[lmr] : (m0 + lmr);
            if (gather && dst < 0) continue;
            half_t* crow = H + (size_t)dst * KD + n0 + warpN * 32 + cbase;
#pragma unroll
            for (int ns = 0; ns < 4; ns++) {
                float g0 = accg[ms][ns][half * 2], g1 = accg[ms][ns][half * 2 + 1];
                float u0 = accu[ms][ns][half * 2], u1 = accu[ms][ns][half * 2 + 1];
                float h0 = u0 / (1.f + expf(-g0));
                float h1 = u1 / (1.f + expf(-g1));
                *(uint32_t*)(crow + ns * 8) = pack_h2(h0, h1);
            }
        }
    }
}

// ---------------- down-proj GEMM ---------------------------------------------
// CTA tile 128m x 128n, warp 64m x 64n. stage: A 16K | B 16K = 32 KB.
__device__ __forceinline__ void stage_load_s(
    uint32_t sbase, const half_t* __restrict__ A, const half_t* __restrict__ W,
    const int* s_src, int m0, int n0, int k0, int tid)
{
#pragma unroll
    for (int i = 0; i < 8; i++) {
        int chunk = tid + i * 128;
        int row = chunk >> 3, cc = chunk & 7;   // row 0..127
        uint32_t off = row * 128 + ((cc * 16) ^ ((row & 7) << 4));
        int arow = s_src ? s_src[row] : (m0 + row);
        cp16(sbase + off, A + (size_t)arow * KD + k0 + cc * 8);
        cp16(sbase + 16384 + off, W + (size_t)(n0 + row) * KD + k0 + cc * 8);
    }
}

__global__ __launch_bounds__(128, 2)
void down_k(const half_t* __restrict__ As, const half_t* __restrict__ Ar,
            float* __restrict__ Cs, float* __restrict__ Cr)
{
    extern __shared__ __align__(1024) char dynsm[];
    __shared__ int s_src[128];
    __shared__ int s_dst[128];

    const int tid = threadIdx.x;
    const int wid = tid >> 5, lane = tid & 31;
    const int n0 = blockIdx.x * 128;
    const int by = blockIdx.y;

    const half_t* A;
    const half_t* W;
    float* C;
    bool gather;
    int m0;
    if (by < 32) {
        gather = false;
        m0 = by * 128;
        A = As;
        W = g_wT + (size_t)2 * KD * KD;    // slot 2
        C = Cs;
    } else {
        gather = true;
        int e = (by - 32) >> 5;
        int mtile = (by - 32) & 31;
        int count = g_counts[e];
        if (mtile * 128 >= count) return;
        m0 = 0;
        A = Ar;
        W = g_wT + (size_t)(19 + e) * KD * KD;
        C = Cr;
        {
            int idx = mtile * 128 + tid;
            if (idx < count) {
                int p = g_lists[e * TOKENS + idx];
                s_dst[tid] = p;
                s_src[tid] = p;
            } else { s_dst[tid] = -1; s_src[tid] = 0; }
        }
        __syncthreads();
    }
    const int* srcp = gather ? s_src : (const int*)nullptr;
    const uint32_t smbase = smem_to_u32(dynsm);

    const int warpM = wid >> 1, warpN = wid & 1;   // 2m x 2n; warp 64m x 64n
    const int mi = lane >> 3, ri = lane & 7;
    const int aRowBase = warpM * 64 + ((mi & 1) << 3) + ri;
    const int aKoff = (mi >> 1) << 4;
    const uint32_t aSwz = (aRowBase & 7) << 4;
    const int bRowBase = warpN * 64 + ((mi >> 1) << 3) + ri;
    const int bKoff = (mi & 1) << 4;
    const uint32_t bSwz = (bRowBase & 7) << 4;

    float acc[4][8][4];
#pragma unroll
    for (int i = 0; i < 4; i++)
#pragma unroll
        for (int j = 0; j < 8; j++)
#pragma unroll
            for (int q = 0; q < 4; q++) acc[i][j][q] = 0.f;

    stage_load_s(smbase, A, W, srcp, m0, n0, 0, tid);
    CP_COMMIT();

    for (int kt = 0; kt < 16; kt++) {
        const uint32_t buf = smbase + (kt & 1) * STAGE_B;
        if (kt < 15) {
            stage_load_s(smbase + ((kt + 1) & 1) * STAGE_B, A, W, srcp, m0, n0,
                         (kt + 1) * 64, tid);
            CP_COMMIT();
            CP_WAIT1();
        } else {
            CP_WAIT0();
        }
        __syncthreads();
#pragma unroll
        for (int ks = 0; ks < 4; ks++) {
            uint32_t a[4][4], b[4][4];
#pragma unroll
            for (int ms = 0; ms < 4; ms++) {
                uint32_t off = (uint32_t)(aRowBase + ms * 16) * 128
                             + (((uint32_t)(ks * 32 + aKoff)) ^ aSwz);
                ldsm4(a[ms], buf + off);
            }
#pragma unroll
            for (int np = 0; np < 4; np++) {
                uint32_t off = (uint32_t)(bRowBase + np * 16) * 128
                             + (((uint32_t)(ks * 32 + bKoff)) ^ bSwz);
                ldsm4(b[np], buf + 16384 + off);
            }
#pragma unroll
            for (int ms = 0; ms < 4; ms++)
#pragma unroll
                for (int ns = 0; ns < 8; ns++) {
                    int np = ns >> 1, h = (ns & 1) << 1;
                    mma16816(acc[ms][ns], a[ms], b[np][h], b[np][h + 1]);
                }
        }
        __syncthreads();
    }

    const int rbase = lane >> 2;
    const int cbase = (lane & 3) * 2;
#pragma unroll
    for (int ms = 0; ms < 4; ms++) {
        int lm = warpM * 64 + ms * 16 + rbase;
#pragma unroll
        for (int half = 0; half < 2; half++) {
            int lmr = lm + half * 8;
            int dst = gather ? s_dst[lmr] : (m0 + lmr);
            if (gather && dst < 0) continue;
            float* crow = C + (size_t)dst * KD + n0 + warpN * 64 + cbase;
#pragma unroll
            for (int ns = 0; ns < 8; ns++) {
                float2 v;
                v.x = acc[ms][ns][half * 2];
                v.y = acc[ms][ns][half * 2 + 1];
                *(float2*)(crow + ns * 8) = v;
            }
        }
    }
}

// ---------------- final combine ----------------------------------------------
__global__ void epilogue_k(const float* __restrict__ x, float* __restrict__ out) {
    int i = blockIdx.x * blockDim.x + threadIdx.x;
    const int W4 = KD / 4;
    int t = i / W4;
    int h4 = i - t * W4;
    float4 xv = ((const float4*)x)[i];
    float4 sh = ((const float4*)g_o_shared)[i];
    float w0 = g_topw[2 * t], w1 = g_topw[2 * t + 1];
    float4 r0 = *((const float4*)g_o_routed + (size_t)(2 * t) * W4 + h4);
    float4 r1 = *((const float4*)g_o_routed + (size_t)(2 * t + 1) * W4 + h4);
    float4 o;
    o.x = xv.x + sh.x + w0 * r0.x + w1 * r1.x;
    o.y = xv.y + sh.y + w0 * r0.y + w1 * r1.y;
    o.z = xv.z + sh.z + w0 * r0.z + w1 * r1.z;
    o.w = xv.w + sh.w + w0 * r0.w + w1 * r1.w;
    ((float4*)out)[i] = o;
}

// ---------------- launch ------------------------------------------------------
extern "C" void kernel_launch(void* const* d_in, const int* in_sizes, int n_in,
                              void* d_out, int out_size) {
    const float* x  = (const float*)d_in[0];
    const float* rw = (const float*)d_in[1];
    const float* sg = (const float*)d_in[2];
    const float* su = (const float*)d_in[3];
    const float* sd = (const float*)d_in[4];
    const float* eg = (const float*)d_in[5];
    const float* eu = (const float*)d_in[6];
    const float* ed = (const float*)d_in[7];
    float* out = (float*)d_out;

    half_t *xh, *hs, *hr;
    float *o_shared, *o_routed;
    cudaGetSymbolAddress((void**)&xh, g_xh);
    cudaGetSymbolAddress((void**)&hs, g_hs);
    cudaGetSymbolAddress((void**)&hr, g_hr);
    cudaGetSymbolAddress((void**)&o_shared, g_o_shared);
    cudaGetSymbolAddress((void**)&o_routed, g_o_routed);

    const int SMSZ = 2 * STAGE_B;   // 64 KB
    cudaFuncSetAttribute(mlp1_k, cudaFuncAttributeMaxDynamicSharedMemorySize, SMSZ);
    cudaFuncSetAttribute(down_k, cudaFuncAttributeMaxDynamicSharedMemorySize, SMSZ);

    zero_counts_k<<<1, 32>>>();
    convert_router_k<<<TOKENS / 8, 256>>>(x, rw);
    transpose_w_k<<<dim3(16, 32, NMAT), 256>>>(sg, su, sd, eg, eu, ed);

    // merged gate+up (shared y<32, routed y>=32), then merged down-proj
    mlp1_k<<<dim3(16, 32 + NE * 32), 128, SMSZ>>>(xh, hs, hr);
    down_k<<<dim3(8, 32 + NE * 32), 128, SMSZ>>>(hs, hr, o_shared, o_routed);

    epilogue_k<<<(TOKENS * KD / 4) / 256, 256>>>(x, out);
}

// round 16
// speedup vs baseline: 1.0601x; 1.0601x over previous
#include <cuda_runtime.h>
#include <cuda_fp16.h>
#include <math.h>
#include <stdint.h>

#define TOKENS 4096
#define NE 8
#define NPAIR 8192
#define KD 1024
#define NMAT 27            // 0 sg, 1 su, 2 sd, 3..10 eg, 11..18 eu, 19..26 ed

typedef __half half_t;

// ---------------- scratch (device globals; no allocations allowed) ----------
__device__ __align__(16) half_t g_xh[(size_t)TOKENS * KD];          // x fp16
__device__ __align__(16) half_t g_wT[(size_t)NMAT * KD * KD];       // W^T fp16
__device__ __align__(16) half_t g_hs[(size_t)TOKENS * KD];          // shared hidden
__device__ __align__(16) half_t g_hr[(size_t)NPAIR * KD];           // routed hidden
__device__ __align__(16) half_t g_os[(size_t)TOKENS * KD];          // shared out fp16
__device__ __align__(16) half_t g_or[(size_t)NPAIR * KD];           // routed out fp16
__device__ float g_topw[NPAIR];
__device__ int   g_counts[NE];
__device__ int   g_lists[NE * TOKENS];

// ---------------- PTX helpers (portable ISA, sm_80+) -------------------------
__device__ __forceinline__ uint32_t smem_to_u32(const void* p) {
    uint32_t a;
    asm("{ .reg .u64 t; cvta.to.shared.u64 t, %1; cvt.u32.u64 %0, t; }" : "=r"(a) : "l"(p));
    return a;
}
__device__ __forceinline__ void cp16(uint32_t dst, const void* src) {
    asm volatile("cp.async.cg.shared.global [%0], [%1], 16;" :: "r"(dst), "l"(src));
}
#define CP_COMMIT() asm volatile("cp.async.commit_group;" ::: "memory")
#define CP_WAIT1()  asm volatile("cp.async.wait_group 1;" ::: "memory")
#define CP_WAIT0()  asm volatile("cp.async.wait_group 0;" ::: "memory")

__device__ __forceinline__ void ldsm4(uint32_t* r, uint32_t addr) {
    asm volatile("ldmatrix.sync.aligned.m8n8.x4.shared.b16 {%0,%1,%2,%3}, [%4];"
                 : "=r"(r[0]), "=r"(r[1]), "=r"(r[2]), "=r"(r[3]) : "r"(addr));
}
__device__ __forceinline__ void mma16816(float* c, const uint32_t* a,
                                         uint32_t b0, uint32_t b1) {
    asm volatile("mma.sync.aligned.m16n8k16.row.col.f32.f16.f16.f32 "
                 "{%0,%1,%2,%3}, {%4,%5,%6,%7}, {%8,%9}, {%0,%1,%2,%3};"
                 : "+f"(c[0]), "+f"(c[1]), "+f"(c[2]), "+f"(c[3])
                 : "r"(a[0]), "r"(a[1]), "r"(a[2]), "r"(a[3]), "r"(b0), "r"(b1));
}
__device__ __forceinline__ uint32_t pack_h2(float a, float b) {
    __half2 h = __floats2half2_rn(a, b);
    return *(uint32_t*)&h;
}

// ---------------- setup -------------------------------------------------------
__global__ void zero_counts_k() { if (threadIdx.x < NE) g_counts[threadIdx.x] = 0; }

// fused: x fp32 -> fp16 conversion AND router softmax/top2/compaction
__global__ __launch_bounds__(256)
void convert_router_k(const float* __restrict__ x, const float* __restrict__ rw) {
    int t = (blockIdx.x * blockDim.x + threadIdx.x) >> 5;
    int lane = threadIdx.x & 31;
    const float* xr = x + (size_t)t * KD;
    float acc[NE];
#pragma unroll
    for (int e = 0; e < NE; e++) acc[e] = 0.f;
#pragma unroll
    for (int i = 0; i < 8; i++) {
        int h = lane * 4 + i * 128;
        float4 v = *(const float4*)(xr + h);
        uint2 p;
        p.x = pack_h2(v.x, v.y);
        p.y = pack_h2(v.z, v.w);
        *(uint2*)(g_xh + (size_t)t * KD + h) = p;
#pragma unroll
        for (int e = 0; e < NE; e++) {
            float4 w = *(const float4*)(rw + e * KD + h);
            acc[e] = fmaf(v.x, w.x, acc[e]);
            acc[e] = fmaf(v.y, w.y, acc[e]);
            acc[e] = fmaf(v.z, w.z, acc[e]);
            acc[e] = fmaf(v.w, w.w, acc[e]);
        }
    }
#pragma unroll
    for (int e = 0; e < NE; e++)
#pragma unroll
        for (int o = 16; o > 0; o >>= 1)
            acc[e] += __shfl_down_sync(0xffffffffu, acc[e], o);
    if (lane == 0) {
        float mx = acc[0];
#pragma unroll
        for (int e = 1; e < NE; e++) mx = fmaxf(mx, acc[e]);
        float s[NE]; float sum = 0.f;
#pragma unroll
        for (int e = 0; e < NE; e++) { s[e] = expf(acc[e] - mx); sum += s[e]; }
        float inv = 1.f / sum;
        int i1 = 0; float v1 = s[0];
#pragma unroll
        for (int e = 1; e < NE; e++) if (s[e] > v1) { v1 = s[e]; i1 = e; }
        int i2 = -1; float v2 = -1.f;
#pragma unroll
        for (int e = 0; e < NE; e++) if (e != i1 && s[e] > v2) { v2 = s[e]; i2 = e; }
        g_topw[t * 2 + 0] = v1 * inv;
        g_topw[t * 2 + 1] = v2 * inv;
        int s1 = atomicAdd(&g_counts[i1], 1); g_lists[i1 * TOKENS + s1] = t * 2;
        int s2 = atomicAdd(&g_counts[i2], 1); g_lists[i2 * TOKENS + s2] = t * 2 + 1;
    }
}

// transpose weights: [K][N] fp32 -> [n][k] fp16
__global__ __launch_bounds__(256) void transpose_w_k(
    const float* __restrict__ sg, const float* __restrict__ su,
    const float* __restrict__ sd, const float* __restrict__ eg,
    const float* __restrict__ eu, const float* __restrict__ ed)
{
    __shared__ float t[64][33];
    int slot = blockIdx.z;
    const float* src;
    if      (slot == 0) src = sg;
    else if (slot == 1) src = su;
    else if (slot == 2) src = sd;
    else if (slot < 11) src = eg + (size_t)(slot - 3) * KD * KD;
    else if (slot < 19) src = eu + (size_t)(slot - 11) * KD * KD;
    else                src = ed + (size_t)(slot - 19) * KD * KD;
    int k0 = blockIdx.x * 64, n0 = blockIdx.y * 32;
    int tx = threadIdx.x & 31, ty = threadIdx.x >> 5;
#pragma unroll
    for (int i = 0; i < 8; i++) {
        int r = ty + i * 8;
        t[r][tx] = src[(size_t)(k0 + r) * KD + n0 + tx];
    }
    __syncthreads();
    half_t* oh = g_wT + (size_t)slot * KD * KD;
#pragma unroll
    for (int i = 0; i < 4; i++) {
        int r = ty + i * 8;
        ((uint32_t*)(oh + (size_t)(n0 + r) * KD + k0))[tx] =
            pack_h2(t[2 * tx][r], t[2 * tx + 1][r]);
    }
}

// ============================================================================
// GEMM kernels — 128-row M tiles, 256-thread CTAs, 4m x 2n warp layout,
// 2 CTAs/SM. y index: [0,32) shared (m0 = y*128); [32, 32+256) routed.
// ============================================================================
#define STAGE_B 32768

// ---------------- mlp1: dual gate+up GEMM with fused SwiGLU ------------------
// CTA tile 128m x 64n per matrix. stage: A 16K | Bg 8K | Bu 8K = 32 KB.
__device__ __forceinline__ void stage_load_d(
    uint32_t sbase, const half_t* __restrict__ A, const half_t* __restrict__ Wg,
    const half_t* __restrict__ Wu, const int* s_src, int m0, int n0, int k0, int tid)
{
#pragma unroll
    for (int i = 0; i < 4; i++) {
        int chunk = tid + i * 256;
        int row = chunk >> 3, cc = chunk & 7;   // row 0..127
        uint32_t off = row * 128 + ((cc * 16) ^ ((row & 7) << 4));
        int arow = s_src ? s_src[row] : (m0 + row);
        cp16(sbase + off, A + (size_t)arow * KD + k0 + cc * 8);
    }
#pragma unroll
    for (int i = 0; i < 2; i++) {
        int chunk = tid + i * 256;
        int row = chunk >> 3, cc = chunk & 7;   // row 0..63
        uint32_t off = row * 128 + ((cc * 16) ^ ((row & 7) << 4));
        cp16(sbase + 16384 + off, Wg + (size_t)(n0 + row) * KD + k0 + cc * 8);
        cp16(sbase + 24576 + off, Wu + (size_t)(n0 + row) * KD + k0 + cc * 8);
    }
}

__global__ __launch_bounds__(256, 2)
void mlp1_k(const half_t* __restrict__ A, half_t* __restrict__ Hs,
            half_t* __restrict__ Hr)
{
    extern __shared__ __align__(1024) char dynsm[];
    __shared__ int s_src[128];
    __shared__ int s_dst[128];

    const int tid = threadIdx.x;
    const int wid = tid >> 5, lane = tid & 31;
    const int n0 = blockIdx.x * 64;
    const int by = blockIdx.y;

    const half_t* Wg;
    const half_t* Wu;
    half_t* H;
    bool gather;
    int m0;
    if (by < 32) {
        gather = false;
        m0 = by * 128;
        Wg = g_wT;                         // slot 0
        Wu = g_wT + (size_t)1 * KD * KD;   // slot 1
        H = Hs;
    } else {
        gather = true;
        int e = (by - 32) >> 5;
        int mtile = (by - 32) & 31;
        int count = g_counts[e];
        if (mtile * 128 >= count) return;
        m0 = 0;
        Wg = g_wT + (size_t)(3 + e) * KD * KD;
        Wu = g_wT + (size_t)(11 + e) * KD * KD;
        H = Hr;
        if (tid < 128) {
            int idx = mtile * 128 + tid;
            if (idx < count) {
                int p = g_lists[e * TOKENS + idx];
                s_dst[tid] = p;
                s_src[tid] = p >> 1;
            } else { s_dst[tid] = -1; s_src[tid] = 0; }
        }
        __syncthreads();
    }
    const int* srcp = gather ? s_src : (const int*)nullptr;
    const uint32_t smbase = smem_to_u32(dynsm);

    const int warpM = wid >> 1, warpN = wid & 1;   // 4m x 2n; warp 32m x 32n/matrix
    const int mi = lane >> 3, ri = lane & 7;
    const int aRowBase = warpM * 32 + ((mi & 1) << 3) + ri;
    const int aKoff = (mi >> 1) << 4;
    const uint32_t aSwz = (aRowBase & 7) << 4;
    const int bRowBase = warpN * 32 + ((mi >> 1) << 3) + ri;
    const int bKoff = (mi & 1) << 4;
    const uint32_t bSwz = (bRowBase & 7) << 4;

    float accg[2][4][4], accu[2][4][4];
#pragma unroll
    for (int i = 0; i < 2; i++)
#pragma unroll
        for (int j = 0; j < 4; j++)
#pragma unroll
            for (int q = 0; q < 4; q++) { accg[i][j][q] = 0.f; accu[i][j][q] = 0.f; }

    stage_load_d(smbase, A, Wg, Wu, srcp, m0, n0, 0, tid);
    CP_COMMIT();

    for (int kt = 0; kt < 16; kt++) {
        const uint32_t buf = smbase + (kt & 1) * STAGE_B;
        if (kt < 15) {
            stage_load_d(smbase + ((kt + 1) & 1) * STAGE_B, A, Wg, Wu, srcp,
                         m0, n0, (kt + 1) * 64, tid);
            CP_COMMIT();
            CP_WAIT1();
        } else {
            CP_WAIT0();
        }
        __syncthreads();
#pragma unroll
        for (int ks = 0; ks < 4; ks++) {
            uint32_t a[2][4], bg[2][4], bu[2][4];
#pragma unroll
            for (int ms = 0; ms < 2; ms++) {
                uint32_t off = (uint32_t)(aRowBase + ms * 16) * 128
                             + (((uint32_t)(ks * 32 + aKoff)) ^ aSwz);
                ldsm4(a[ms], buf + off);
            }
#pragma unroll
            for (int np = 0; np < 2; np++) {
                uint32_t off = (uint32_t)(bRowBase + np * 16) * 128
                             + (((uint32_t)(ks * 32 + bKoff)) ^ bSwz);
                ldsm4(bg[np], buf + 16384 + off);
                ldsm4(bu[np], buf + 24576 + off);
            }
#pragma unroll
            for (int ms = 0; ms < 2; ms++)
#pragma unroll
                for (int ns = 0; ns < 4; ns++) {
                    int np = ns >> 1, h = (ns & 1) << 1;
                    mma16816(accg[ms][ns], a[ms], bg[np][h], bg[np][h + 1]);
                    mma16816(accu[ms][ns], a[ms], bu[np][h], bu[np][h + 1]);
                }
        }
        __syncthreads();
    }

    const int rbase = lane >> 2;
    const int cbase = (lane & 3) * 2;
#pragma unroll
    for (int ms = 0; ms < 2; ms++) {
        int lm = warpM * 32 + ms * 16 + rbase;
#pragma unroll
        for (int half = 0; half < 2; half++) {
            int lmr = lm + half * 8;
            int dst = gather ? s_dst[lmr] : (m0 + lmr);
            if (gather && dst < 0) continue;
            half_t* crow = H + (size_t)dst * KD + n0 + warpN * 32 + cbase;
#pragma unroll
            for (int ns = 0; ns < 4; ns++) {
                float g0 = accg[ms][ns][half * 2], g1 = accg[ms][ns][half * 2 + 1];
                float u0 = accu[ms][ns][half * 2], u1 = accu[ms][ns][half * 2 + 1];
                float h0 = __fdividef(u0, 1.f + __expf(-g0));
                float h1 = __fdividef(u1, 1.f + __expf(-g1));
                *(uint32_t*)(crow + ns * 8) = pack_h2(h0, h1);
            }
        }
    }
}

// ---------------- down-proj GEMM (fp16 output) -------------------------------
// CTA tile 128m x 128n, warp 32m x 64n. stage: A 16K | B 16K = 32 KB.
__device__ __forceinline__ void stage_load_s(
    uint32_t sbase, const half_t* __restrict__ A, const half_t* __restrict__ W,
    const int* s_src, int m0, int n0, int k0, int tid)
{
#pragma unroll
    for (int i = 0; i < 4; i++) {
        int chunk = tid + i * 256;
        int row = chunk >> 3, cc = chunk & 7;   // row 0..127
        uint32_t off = row * 128 + ((cc * 16) ^ ((row & 7) << 4));
        int arow = s_src ? s_src[row] : (m0 + row);
        cp16(sbase + off, A + (size_t)arow * KD + k0 + cc * 8);
        cp16(sbase + 16384 + off, W + (size_t)(n0 + row) * KD + k0 + cc * 8);
    }
}

__global__ __launch_bounds__(256, 2)
void down_k(const half_t* __restrict__ As, const half_t* __restrict__ Ar,
            half_t* __restrict__ Cs, half_t* __restrict__ Cr)
{
    extern __shared__ __align__(1024) char dynsm[];
    __shared__ int s_src[128];
    __shared__ int s_dst[128];

    const int tid = threadIdx.x;
    const int wid = tid >> 5, lane = tid & 31;
    const int n0 = blockIdx.x * 128;
    const int by = blockIdx.y;

    const half_t* A;
    const half_t* W;
    half_t* C;
    bool gather;
    int m0;
    if (by < 32) {
        gather = false;
        m0 = by * 128;
        A = As;
        W = g_wT + (size_t)2 * KD * KD;    // slot 2
        C = Cs;
    } else {
        gather = true;
        int e = (by - 32) >> 5;
        int mtile = (by - 32) & 31;
        int count = g_counts[e];
        if (mtile * 128 >= count) return;
        m0 = 0;
        A = Ar;
        W = g_wT + (size_t)(19 + e) * KD * KD;
        C = Cr;
        if (tid < 128) {
            int idx = mtile * 128 + tid;
            if (idx < count) {
                int p = g_lists[e * TOKENS + idx];
                s_dst[tid] = p;
                s_src[tid] = p;
            } else { s_dst[tid] = -1; s_src[tid] = 0; }
        }
        __syncthreads();
    }
    const int* srcp = gather ? s_src : (const int*)nullptr;
    const uint32_t smbase = smem_to_u32(dynsm);

    const int warpM = wid >> 1, warpN = wid & 1;   // 4m x 2n; warp 32m x 64n
    const int mi = lane >> 3, ri = lane & 7;
    const int aRowBase = warpM * 32 + ((mi & 1) << 3) + ri;
    const int aKoff = (mi >> 1) << 4;
    const uint32_t aSwz = (aRowBase & 7) << 4;
    const int bRowBase = warpN * 64 + ((mi >> 1) << 3) + ri;
    const int bKoff = (mi & 1) << 4;
    const uint32_t bSwz = (bRowBase & 7) << 4;

    float acc[2][8][4];
#pragma unroll
    for (int i = 0; i < 2; i++)
#pragma unroll
        for (int j = 0; j < 8; j++)
#pragma unroll
            for (int q = 0; q < 4; q++) acc[i][j][q] = 0.f;

    stage_load_s(smbase, A, W, srcp, m0, n0, 0, tid);
    CP_COMMIT();

    for (int kt = 0; kt < 16; kt++) {
        const uint32_t buf = smbase + (kt & 1) * STAGE_B;
        if (kt < 15) {
            stage_load_s(smbase + ((kt + 1) & 1) * STAGE_B, A, W, srcp, m0, n0,
                         (kt + 1) * 64, tid);
            CP_COMMIT();
            CP_WAIT1();
        } else {
            CP_WAIT0();
        }
        __syncthreads();
#pragma unroll
        for (int ks = 0; ks < 4; ks++) {
            uint32_t a[2][4], b[4][4];
#pragma unroll
            for (int ms = 0; ms < 2; ms++) {
                uint32_t off = (uint32_t)(aRowBase + ms * 16) * 128
                             + (((uint32_t)(ks * 32 + aKoff)) ^ aSwz);
                ldsm4(a[ms], buf + off);
            }
#pragma unroll
            for (int np = 0; np < 4; np++) {
                uint32_t off = (uint32_t)(bRowBase + np * 16) * 128
                             + (((uint32_t)(ks * 32 + bKoff)) ^ bSwz);
                ldsm4(b[np], buf + 16384 + off);
            }
#pragma unroll
            for (int ms = 0; ms < 2; ms++)
#pragma unroll
                for (int ns = 0; ns < 8; ns++) {
                    int np = ns >> 1, h = (ns & 1) << 1;
                    mma16816(acc[ms][ns], a[ms], b[np][h], b[np][h + 1]);
                }
        }
        __syncthreads();
    }

    const int rbase = lane >> 2;
    const int cbase = (lane & 3) * 2;
#pragma unroll
    for (int ms = 0; ms < 2; ms++) {
        int lm = warpM * 32 + ms * 16 + rbase;
#pragma unroll
        for (int half = 0; half < 2; half++) {
            int lmr = lm + half * 8;
            int dst = gather ? s_dst[lmr] : (m0 + lmr);
            if (gather && dst < 0) continue;
            half_t* crow = C + (size_t)dst * KD + n0 + warpN * 64 + cbase;
#pragma unroll
            for (int ns = 0; ns < 8; ns++) {
                *(uint32_t*)(crow + ns * 8) =
                    pack_h2(acc[ms][ns][half * 2], acc[ms][ns][half * 2 + 1]);
            }
        }
    }
}

// ---------------- final combine ----------------------------------------------
__global__ void epilogue_k(const float* __restrict__ x, float* __restrict__ out) {
    int i = blockIdx.x * blockDim.x + threadIdx.x;   // float4 index
    const int W4 = KD / 4;
    int t = i / W4;
    int h4 = i - t * W4;
    float4 xv = ((const float4*)x)[i];
    uint2 shp = ((const uint2*)g_os)[i];
    __half2 sh0 = *(__half2*)&shp.x, sh1 = *(__half2*)&shp.y;
    float w0 = g_topw[2 * t], w1 = g_topw[2 * t + 1];
    uint2 r0p = *((const uint2*)g_or + (size_t)(2 * t) * W4 + h4);
    uint2 r1p = *((const uint2*)g_or + (size_t)(2 * t + 1) * W4 + h4);
    __half2 r00 = *(__half2*)&r0p.x, r01 = *(__half2*)&r0p.y;
    __half2 r10 = *(__half2*)&r1p.x, r11 = *(__half2*)&r1p.y;
    float2 s0 = __half22float2(sh0), s1 = __half22float2(sh1);
    float2 a0 = __half22float2(r00), a1 = __half22float2(r01);
    float2 b0 = __half22float2(r10), b1 = __half22float2(r11);
    float4 o;
    o.x = xv.x + s0.x + w0 * a0.x + w1 * b0.x;
    o.y = xv.y + s0.y + w0 * a0.y + w1 * b0.y;
    o.z = xv.z + s1.x + w0 * a1.x + w1 * b1.x;
    o.w = xv.w + s1.y + w0 * a1.y + w1 * b1.y;
    ((float4*)out)[i] = o;
}

// ---------------- launch ------------------------------------------------------
extern "C" void kernel_launch(void* const* d_in, const int* in_sizes, int n_in,
                              void* d_out, int out_size) {
    const float* x  = (const float*)d_in[0];
    const float* rw = (const float*)d_in[1];
    const float* sg = (const float*)d_in[2];
    const float* su = (const float*)d_in[3];
    const float* sd = (const float*)d_in[4];
    const float* eg = (const float*)d_in[5];
    const float* eu = (const float*)d_in[6];
    const float* ed = (const float*)d_in[7];
    float* out = (float*)d_out;

    half_t *xh, *hs, *hr, *os, *orr;
    cudaGetSymbolAddress((void**)&xh, g_xh);
    cudaGetSymbolAddress((void**)&hs, g_hs);
    cudaGetSymbolAddress((void**)&hr, g_hr);
    cudaGetSymbolAddress((void**)&os, g_os);
    cudaGetSymbolAddress((void**)&orr, g_or);

    const int SMSZ = 2 * STAGE_B;   // 64 KB
    cudaFuncSetAttribute(mlp1_k, cudaFuncAttributeMaxDynamicSharedMemorySize, SMSZ);
    cudaFuncSetAttribute(down_k, cudaFuncAttributeMaxDynamicSharedMemorySize, SMSZ);

    zero_counts_k<<<1, 32>>>();
    convert_router_k<<<TOKENS / 8, 256>>>(x, rw);
    transpose_w_k<<<dim3(16, 32, NMAT), 256>>>(sg, su, sd, eg, eu, ed);

    // merged gate+up (shared y<32, routed y>=32), then merged down-proj
    mlp1_k<<<dim3(16, 32 + NE * 32), 256, SMSZ>>>(xh, hs, hr);
    down_k<<<dim3(8, 32 + NE * 32), 256, SMSZ>>>(hs, hr, os, orr);

    epilogue_k<<<(TOKENS * KD / 4) / 256, 256>>>(x, out);
}